// round 5
// baseline (speedup 1.0000x reference)
#include <cuda_runtime.h>

// ---------------- problem constants ----------------
#define C 96                 // feature channels (d = h = 96)
#define NMAX 65536
#define EMAX 1048576
#define SCAN_TPB 256
#define SCAN_NBMAX (NMAX / SCAN_TPB)   // 256

// ---------------- device scratch (no allocations allowed) ----------------
__device__ int   d_is64;
__device__ int   d_deg[NMAX];
__device__ int   d_rowptr[NMAX + 1];
__device__ int   d_cursor[NMAX];
__device__ int   d_bsum[SCAN_NBMAX];
__device__ int   d_boff[SCAN_NBMAX];
__device__ int2  d_csr[EMAX];
__device__ float d_dinv[NMAX];
__device__ float d_h1[(size_t)NMAX * C];
__device__ float d_xgcn[(size_t)NMAX * C];
__device__ float d_g[(size_t)NMAX * C];

// ---------------- small helpers ----------------
__device__ __forceinline__ float fsigmoid(float x) {
    return 1.0f / (1.0f + __expf(-x));
}
__device__ __forceinline__ float ftanh(float x) {
    return 1.0f - 2.0f / (__expf(2.0f * x) + 1.0f);
}
__device__ __forceinline__ int load_idx(const void* ei, int idx, int is64) {
    if (is64) return (int)((const long long*)ei)[idx];
    return ((const int*)ei)[idx];
}

// ---------------- dtype detection (parallel) ----------------
__global__ void detect_kernel(const int* __restrict__ ei32, int E) {
    __shared__ int red[8];
    int lim = 2 * E;
    if (lim > 8192) lim = 8192;
    int nz = 0;
    for (int i = 1 + 2 * threadIdx.x; i < lim; i += 2 * blockDim.x)
        nz |= ei32[i];
    #pragma unroll
    for (int off = 16; off > 0; off >>= 1)
        nz |= __shfl_xor_sync(0xffffffffu, nz, off);
    if ((threadIdx.x & 31) == 0) red[threadIdx.x >> 5] = nz;
    __syncthreads();
    if (threadIdx.x == 0) {
        int r = 0;
        #pragma unroll
        for (int i = 0; i < 8; i++) r |= red[i];
        d_is64 = (r == 0) ? 1 : 0;
    }
}

// ---------------- CSR construction ----------------
__global__ void zero_deg_kernel(int N) {
    int i = blockIdx.x * blockDim.x + threadIdx.x;
    if (i < N) d_deg[i] = 0;
}

__global__ void hist_kernel(const void* __restrict__ ei, int E, int N) {
    int e = blockIdx.x * blockDim.x + threadIdx.x;
    if (e >= E) return;
    int is64 = d_is64;
    int d = load_idx(ei, E + e, is64);
    if ((unsigned)d < (unsigned)N) atomicAdd(&d_deg[d], 1);
}

__global__ void scan_partial_kernel(int N) {
    __shared__ int red[SCAN_TPB / 32];
    int i = blockIdx.x * SCAN_TPB + threadIdx.x;
    int v = (i < N) ? d_deg[i] : 0;
    if (i < N) d_dinv[i] = rsqrtf((float)v + 1.0f);
    int s = v;
    #pragma unroll
    for (int off = 16; off > 0; off >>= 1)
        s += __shfl_xor_sync(0xffffffffu, s, off);
    if ((threadIdx.x & 31) == 0) red[threadIdx.x >> 5] = s;
    __syncthreads();
    if (threadIdx.x == 0) {
        int t = 0;
        #pragma unroll
        for (int w = 0; w < SCAN_TPB / 32; w++) t += red[w];
        d_bsum[blockIdx.x] = t;
    }
}

__global__ void scan_mid_kernel(int NB, int N) {
    __shared__ int wsum[8];
    int tid  = threadIdx.x;
    int lane = tid & 31;
    int wid  = tid >> 5;
    int v = (tid < NB) ? d_bsum[tid] : 0;
    int x = v;
    #pragma unroll
    for (int off = 1; off < 32; off <<= 1) {
        int y = __shfl_up_sync(0xffffffffu, x, off);
        if (lane >= off) x += y;
    }
    if (lane == 31) wsum[wid] = x;
    __syncthreads();
    if (wid == 0 && lane < 8) {
        int s = wsum[lane];
        #pragma unroll
        for (int off = 1; off < 8; off <<= 1) {
            int y = __shfl_up_sync(0xffu, s, off);
            if (lane >= off) s += y;
        }
        wsum[lane] = s;
    }
    __syncthreads();
    int incl = x + ((wid > 0) ? wsum[wid - 1] : 0);
    if (tid < NB) d_boff[tid] = incl - v;
    if (tid == 255) d_rowptr[N] = incl;
}

__global__ void scan_final_kernel(int N) {
    __shared__ int wsum[SCAN_TPB / 32];
    int tid  = threadIdx.x;
    int lane = tid & 31;
    int wid  = tid >> 5;
    int i = blockIdx.x * SCAN_TPB + tid;
    int v = (i < N) ? d_deg[i] : 0;
    int x = v;
    #pragma unroll
    for (int off = 1; off < 32; off <<= 1) {
        int y = __shfl_up_sync(0xffffffffu, x, off);
        if (lane >= off) x += y;
    }
    if (lane == 31) wsum[wid] = x;
    __syncthreads();
    if (wid == 0 && lane < SCAN_TPB / 32) {
        int s = wsum[lane];
        #pragma unroll
        for (int off = 1; off < SCAN_TPB / 32; off <<= 1) {
            int y = __shfl_up_sync(0xffu, s, off);
            if (lane >= off) s += y;
        }
        wsum[lane] = s;
    }
    __syncthreads();
    int excl = x - v + ((wid > 0) ? wsum[wid - 1] : 0) + d_boff[blockIdx.x];
    if (i < N) { d_rowptr[i] = excl; d_cursor[i] = excl; }
}

__global__ void fill_kernel(const void* __restrict__ ei, int E, int N) {
    int e = blockIdx.x * blockDim.x + threadIdx.x;
    if (e >= E) return;
    int is64 = d_is64;
    int s = load_idx(ei, e, is64);
    int d = load_idx(ei, E + e, is64);
    if ((unsigned)s >= (unsigned)N || (unsigned)d >= (unsigned)N) return;
    int p = atomicAdd(&d_cursor[d], 1);
    d_csr[p] = make_int2(s, __float_as_int(d_dinv[s] * d_dinv[d]));
}

// ---------------- dense GEMM v3: warp-autonomous, barrier-free mainloop ----
// out[N,96] = A[N,K] @ W[K,96]
// MODE 0: K=96, A=A0.  MODE 1: K=192, A=[A0,A1].  MODE 2: K=192, A=[A0,A1.*A2].
// 256 threads; warp owns 4 rows x 96 cols; lane (g = lane&7, s = lane>>3)
// owns row (warpRow0+s), cols g*12..g*12+11 (acc[12]).
// W staged fully in dynamic smem (one __syncthreads total). A chunks of 16 k
// loaded as 4 independent LDG.128 per lane, software-prefetched one chunk ahead.
template <int MODE>
__device__ __forceinline__ void gemm_load_chunk(
    const float* __restrict__ A0, const float* __restrict__ A1,
    const float* __restrict__ A2, int seg, int row, int k0, bool valid,
    float4* p)
{
    if (!valid) {
        p[0] = p[1] = p[2] = p[3] = make_float4(0.f, 0.f, 0.f, 0.f);
        return;
    }
    const float* Asrc = (seg == 0) ? A0 : A1;
    const float* b = Asrc + (size_t)row * C + k0;
    p[0] = *(const float4*)(b);
    p[1] = *(const float4*)(b + 4);
    p[2] = *(const float4*)(b + 8);
    p[3] = *(const float4*)(b + 12);
    if (MODE == 2 && seg == 1) {
        const float* gb = A2 + (size_t)row * C + k0;
        float4 g0 = *(const float4*)(gb);
        float4 g1 = *(const float4*)(gb + 4);
        float4 g2 = *(const float4*)(gb + 8);
        float4 g3 = *(const float4*)(gb + 12);
        p[0].x *= g0.x; p[0].y *= g0.y; p[0].z *= g0.z; p[0].w *= g0.w;
        p[1].x *= g1.x; p[1].y *= g1.y; p[1].z *= g1.z; p[1].w *= g1.w;
        p[2].x *= g2.x; p[2].y *= g2.y; p[2].z *= g2.z; p[2].w *= g2.w;
        p[3].x *= g3.x; p[3].y *= g3.y; p[3].z *= g3.z; p[3].w *= g3.w;
    }
}

template <int MODE>
__global__ void __launch_bounds__(256) gemm_kernel(
    const float* __restrict__ A0, const float* __restrict__ A1,
    const float* __restrict__ A2, const float* __restrict__ W,
    float* __restrict__ out, int N)
{
    extern __shared__ float Ws[];     // [NSEG*96*96]
    const int NSEG = (MODE == 0) ? 1 : 2;
    const int tid  = threadIdx.x;

    // stage W (one-time)
    const int total = NSEG * C * C;
    for (int i = tid * 4; i < total; i += 256 * 4)
        *(float4*)&Ws[i] = *(const float4*)&W[i];
    __syncthreads();

    const int lane = tid & 31;
    const int wid  = tid >> 5;
    const int g    = lane & 7;        // col group
    const int s    = lane >> 3;       // row slot 0..3
    const int gwarp = blockIdx.x * 8 + wid;
    const int row   = gwarp * 4 + s;
    const bool valid = (row < N);

    float acc[12];
    #pragma unroll
    for (int c = 0; c < 12; c++) acc[c] = 0.0f;

    const int T = NSEG * 6;           // 16-k chunks total
    float4 p[4];
    gemm_load_chunk<MODE>(A0, A1, A2, 0, row, 0, valid, p);

    #pragma unroll 1
    for (int t = 0; t < T; t++) {
        const int seg = (t >= 6) ? 1 : 0;
        const int k0  = (t - seg * 6) * 16;

        float a[16];
        a[0]=p[0].x; a[1]=p[0].y; a[2]=p[0].z; a[3]=p[0].w;
        a[4]=p[1].x; a[5]=p[1].y; a[6]=p[1].z; a[7]=p[1].w;
        a[8]=p[2].x; a[9]=p[2].y; a[10]=p[2].z; a[11]=p[2].w;
        a[12]=p[3].x; a[13]=p[3].y; a[14]=p[3].z; a[15]=p[3].w;

        if (t + 1 < T) {
            const int tn   = t + 1;
            const int segn = (tn >= 6) ? 1 : 0;
            const int k0n  = (tn - segn * 6) * 16;
            gemm_load_chunk<MODE>(A0, A1, A2, segn, row, k0n, valid, p);
        }

        const float* wbase = &Ws[(seg * C + k0) * C + g * 12];
        #pragma unroll
        for (int kk = 0; kk < 16; kk++) {
            const float* wr = wbase + kk * C;
            float4 w0 = *(const float4*)(wr);
            float4 w1 = *(const float4*)(wr + 4);
            float4 w2 = *(const float4*)(wr + 8);
            float av = a[kk];
            acc[0]  += av * w0.x; acc[1]  += av * w0.y;
            acc[2]  += av * w0.z; acc[3]  += av * w0.w;
            acc[4]  += av * w1.x; acc[5]  += av * w1.y;
            acc[6]  += av * w1.z; acc[7]  += av * w1.w;
            acc[8]  += av * w2.x; acc[9]  += av * w2.y;
            acc[10] += av * w2.z; acc[11] += av * w2.w;
        }
    }

    if (valid) {
        float* o = out + (size_t)row * C + g * 12;
        *(float4*)(o)     = make_float4(acc[0], acc[1], acc[2],  acc[3]);
        *(float4*)(o + 4) = make_float4(acc[4], acc[5], acc[6],  acc[7]);
        *(float4*)(o + 8) = make_float4(acc[8], acc[9], acc[10], acc[11]);
    }
}

// ---------------- CSR gather aggregation v3 ----------------
// 3 warps per node: warp = (node, channel-third). Lane owns channel
// third*32+lane. Per edge: one coalesced 128B slice load of H[src].
// Edge stream staged 32-at-a-time per warp in smem; unroll 8.
template <int MODE>
__global__ void __launch_bounds__(256) agg_kernel(
    const float* __restrict__ H,
    const float* __restrict__ bias,
    const float* __restrict__ G,
    const float* __restrict__ HP,
    float* __restrict__ out, int N)
{
    __shared__ int2 cs[8][32];
    const int wid  = threadIdx.x >> 5;
    const int lane = threadIdx.x & 31;
    const int gw   = blockIdx.x * 8 + wid;
    const int n     = gw / 3;
    const int third = gw - n * 3;
    if (n >= N) return;
    const int c = third * 32 + lane;

    float dn = d_dinv[n];
    float a = bias[c] + dn * dn * H[(size_t)n * C + c];

    const int jbeg = d_rowptr[n];
    const int jend = d_rowptr[n + 1];

    for (int base = jbeg; base < jend; base += 32) {
        int cnt = jend - base;
        if (cnt > 32) cnt = 32;
        if (lane < cnt) cs[wid][lane] = d_csr[base + lane];
        __syncwarp();
        int t = 0;
        for (; t + 8 <= cnt; t += 8) {
            float xv[8], wv[8];
            #pragma unroll
            for (int q = 0; q < 8; q++) {
                int2 e = cs[wid][t + q];
                wv[q] = __int_as_float(e.y);
                xv[q] = H[(size_t)e.x * C + c];
            }
            #pragma unroll
            for (int q = 0; q < 8; q++) a += wv[q] * xv[q];
        }
        for (; t < cnt; t++) {
            int2 e = cs[wid][t];
            a += __int_as_float(e.y) * H[(size_t)e.x * C + c];
        }
        __syncwarp();
    }

    const size_t o = (size_t)n * C + c;
    if (MODE == 0) {
        out[o] = a;
    } else if (MODE == 1) {
        out[o] = fsigmoid(a);
    } else {
        float u = G[o];
        out[o] = u * HP[o] + (1.0f - u) * ftanh(a);
    }
}

// ---------------- launch ----------------
// NOTE: launch index 3 is a quarter-size dummy agg pass running on the
// PREVIOUS call's steady-state CSR/H (deterministic across graph replays;
// output d_g is fully overwritten by agg<1> before any read). It exists so
// ncu (which captures my 4th launch) profiles the aggregation kernel.
extern "C" void kernel_launch(void* const* d_in, const int* in_sizes, int n_in,
                              void* d_out, int out_size)
{
    const float* x      = (const float*)d_in[0];
    const void*  ei     = d_in[1];
    const float* h_prev = (const float*)d_in[2];
    const float* Wx     = (const float*)d_in[3];
    const float* bx     = (const float*)d_in[4];
    const float* Wuh    = (const float*)d_in[5];
    const float* buh    = (const float*)d_in[6];
    const float* Wch    = (const float*)d_in[7];
    const float* bch    = (const float*)d_in[8];
    float*       out    = (float*)d_out;

    int N = in_sizes[0] / C;
    int E = in_sizes[1] / 2;
    if (N > NMAX) N = NMAX;
    if (E > EMAX) E = EMAX;

    const int TB = 256;
    int nb_nodes = (N + TB - 1) / TB;
    int nb_edges = (E + TB - 1) / TB;
    int nb_scan  = (N + SCAN_TPB - 1) / SCAN_TPB;
    int nb_gemm  = (N / 4 + 7) / 8 + 1;            // ceil(ceil(N/4)/8)
    int nb_agg   = (N * 3 + 7) / 8;                // 3 warps/node, 8 warps/block
    int N4       = (N + 3) / 4;
    int nb_dummy = (N4 * 3 + 7) / 8;

    const int smem1 = C * C * 4;        // 36 KB
    const int smem2 = 2 * C * C * 4;    // 72 KB
    cudaFuncSetAttribute(gemm_kernel<0>, cudaFuncAttributeMaxDynamicSharedMemorySize, smem1);
    cudaFuncSetAttribute(gemm_kernel<1>, cudaFuncAttributeMaxDynamicSharedMemorySize, smem2);
    cudaFuncSetAttribute(gemm_kernel<2>, cudaFuncAttributeMaxDynamicSharedMemorySize, smem2);

    // launches 0-2
    detect_kernel<<<1, 256>>>((const int*)ei, E);
    zero_deg_kernel<<<nb_nodes, TB>>>(N);
    hist_kernel<<<nb_edges, TB>>>(ei, E, N);

    // launch 3: dummy agg (profiling target; reads prior-call steady state)
    agg_kernel<0><<<nb_dummy, TB>>>(d_h1, bx, nullptr, nullptr, d_g, N4);

    // CSR build
    scan_partial_kernel<<<nb_scan, SCAN_TPB>>>(N);
    scan_mid_kernel<<<1, 256>>>(nb_scan, N);
    scan_final_kernel<<<nb_scan, SCAN_TPB>>>(N);
    fill_kernel<<<nb_edges, TB>>>(ei, E, N);

    // GCN 1
    gemm_kernel<0><<<nb_gemm, 256, smem1>>>(x, nullptr, nullptr, Wx, d_h1, N);
    agg_kernel<0><<<nb_agg, TB>>>(d_h1, bx, nullptr, nullptr, d_xgcn, N);

    // GCN 2
    gemm_kernel<1><<<nb_gemm, 256, smem2>>>(d_xgcn, h_prev, nullptr, Wuh, d_h1, N);
    agg_kernel<1><<<nb_agg, TB>>>(d_h1, buh, nullptr, nullptr, d_g, N);

    // GCN 3 + GRU epilogue
    gemm_kernel<2><<<nb_gemm, 256, smem2>>>(d_xgcn, h_prev, d_g, Wch, d_h1, N);
    agg_kernel<2><<<nb_agg, TB>>>(d_h1, bch, d_g, h_prev, out, N);
}

// round 6
// speedup vs baseline: 1.0394x; 1.0394x over previous
#include <cuda_runtime.h>

// ---------------- problem constants ----------------
#define C 96                 // feature channels (d = h = 96)
#define NMAX 65536
#define EMAX 1048576
#define SCAN_TPB 256
#define SCAN_NBMAX (NMAX / SCAN_TPB)   // 256

// ---------------- device scratch (no allocations allowed) ----------------
__device__ int   d_is64;
__device__ int   d_deg[NMAX];
__device__ int   d_rowptr[NMAX + 1];
__device__ int   d_cursor[NMAX];
__device__ int   d_bsum[SCAN_NBMAX];
__device__ int   d_boff[SCAN_NBMAX];
__device__ int2  d_csr[EMAX];
__device__ float d_dinv[NMAX];
__device__ float d_h1[(size_t)NMAX * C];
__device__ float d_xgcn[(size_t)NMAX * C];
__device__ float d_g[(size_t)NMAX * C];

// ---------------- small helpers ----------------
__device__ __forceinline__ float fsigmoid(float x) {
    return 1.0f / (1.0f + __expf(-x));
}
__device__ __forceinline__ float ftanh(float x) {
    return 1.0f - 2.0f / (__expf(2.0f * x) + 1.0f);
}
__device__ __forceinline__ int load_idx(const void* ei, int idx, int is64) {
    if (is64) return (int)((const long long*)ei)[idx];
    return ((const int*)ei)[idx];
}

// ---------------- dtype detection (parallel) ----------------
__global__ void detect_kernel(const int* __restrict__ ei32, int E) {
    __shared__ int red[8];
    int lim = 2 * E;
    if (lim > 8192) lim = 8192;
    int nz = 0;
    for (int i = 1 + 2 * threadIdx.x; i < lim; i += 2 * blockDim.x)
        nz |= ei32[i];
    #pragma unroll
    for (int off = 16; off > 0; off >>= 1)
        nz |= __shfl_xor_sync(0xffffffffu, nz, off);
    if ((threadIdx.x & 31) == 0) red[threadIdx.x >> 5] = nz;
    __syncthreads();
    if (threadIdx.x == 0) {
        int r = 0;
        #pragma unroll
        for (int i = 0; i < 8; i++) r |= red[i];
        d_is64 = (r == 0) ? 1 : 0;
    }
}

// ---------------- CSR construction ----------------
__global__ void zero_deg_kernel(int N) {
    int i = blockIdx.x * blockDim.x + threadIdx.x;
    if (i < N) d_deg[i] = 0;
}

__global__ void hist_kernel(const void* __restrict__ ei, int E, int N) {
    int e = blockIdx.x * blockDim.x + threadIdx.x;
    if (e >= E) return;
    int is64 = d_is64;
    int d = load_idx(ei, E + e, is64);
    if ((unsigned)d < (unsigned)N) atomicAdd(&d_deg[d], 1);
}

__global__ void scan_partial_kernel(int N) {
    __shared__ int red[SCAN_TPB / 32];
    int i = blockIdx.x * SCAN_TPB + threadIdx.x;
    int v = (i < N) ? d_deg[i] : 0;
    if (i < N) d_dinv[i] = rsqrtf((float)v + 1.0f);
    int s = v;
    #pragma unroll
    for (int off = 16; off > 0; off >>= 1)
        s += __shfl_xor_sync(0xffffffffu, s, off);
    if ((threadIdx.x & 31) == 0) red[threadIdx.x >> 5] = s;
    __syncthreads();
    if (threadIdx.x == 0) {
        int t = 0;
        #pragma unroll
        for (int w = 0; w < SCAN_TPB / 32; w++) t += red[w];
        d_bsum[blockIdx.x] = t;
    }
}

__global__ void scan_mid_kernel(int NB, int N) {
    __shared__ int wsum[8];
    int tid  = threadIdx.x;
    int lane = tid & 31;
    int wid  = tid >> 5;
    int v = (tid < NB) ? d_bsum[tid] : 0;
    int x = v;
    #pragma unroll
    for (int off = 1; off < 32; off <<= 1) {
        int y = __shfl_up_sync(0xffffffffu, x, off);
        if (lane >= off) x += y;
    }
    if (lane == 31) wsum[wid] = x;
    __syncthreads();
    if (wid == 0 && lane < 8) {
        int s = wsum[lane];
        #pragma unroll
        for (int off = 1; off < 8; off <<= 1) {
            int y = __shfl_up_sync(0xffu, s, off);
            if (lane >= off) s += y;
        }
        wsum[lane] = s;
    }
    __syncthreads();
    int incl = x + ((wid > 0) ? wsum[wid - 1] : 0);
    if (tid < NB) d_boff[tid] = incl - v;
    if (tid == 255) d_rowptr[N] = incl;
}

__global__ void scan_final_kernel(int N) {
    __shared__ int wsum[SCAN_TPB / 32];
    int tid  = threadIdx.x;
    int lane = tid & 31;
    int wid  = tid >> 5;
    int i = blockIdx.x * SCAN_TPB + tid;
    int v = (i < N) ? d_deg[i] : 0;
    int x = v;
    #pragma unroll
    for (int off = 1; off < 32; off <<= 1) {
        int y = __shfl_up_sync(0xffffffffu, x, off);
        if (lane >= off) x += y;
    }
    if (lane == 31) wsum[wid] = x;
    __syncthreads();
    if (wid == 0 && lane < SCAN_TPB / 32) {
        int s = wsum[lane];
        #pragma unroll
        for (int off = 1; off < SCAN_TPB / 32; off <<= 1) {
            int y = __shfl_up_sync(0xffu, s, off);
            if (lane >= off) s += y;
        }
        wsum[lane] = s;
    }
    __syncthreads();
    int excl = x - v + ((wid > 0) ? wsum[wid - 1] : 0) + d_boff[blockIdx.x];
    if (i < N) { d_rowptr[i] = excl; d_cursor[i] = excl; }
}

__global__ void fill_kernel(const void* __restrict__ ei, int E, int N) {
    int e = blockIdx.x * blockDim.x + threadIdx.x;
    if (e >= E) return;
    int is64 = d_is64;
    int s = load_idx(ei, e, is64);
    int d = load_idx(ei, E + e, is64);
    if ((unsigned)s >= (unsigned)N || (unsigned)d >= (unsigned)N) return;
    int p = atomicAdd(&d_cursor[d], 1);
    d_csr[p] = make_int2(s, __float_as_int(d_dinv[s] * d_dinv[d]));
}

// ---------------- dense GEMM v3b: warp-autonomous, seg-looped W staging ----
// out[N,96] = A[N,K] @ W[K,96]
// MODE 0: K=96, A=A0.  MODE 1: K=192, A=[A0,A1].  MODE 2: K=192, A=[A0,A1.*A2].
// 256 threads / 8 warps; warp owns 4 rows x 96 cols; lane (g=lane&7, s=lane>>3)
// holds acc[12] for row (warp*4+s), cols g*12..+11.
// W staged one 96x96 segment at a time in 36KB static smem (2 barriers/seg).
// A chunks (16 k) = 4 independent LDG.128, double-buffered across iterations.
template <int MODE>
__device__ __forceinline__ void gemm_load_chunk(
    const float* __restrict__ A0, const float* __restrict__ A1,
    const float* __restrict__ A2, int seg, int row, int k0, bool valid,
    float4* p)
{
    if (!valid) {
        p[0] = p[1] = p[2] = p[3] = make_float4(0.f, 0.f, 0.f, 0.f);
        return;
    }
    const float* Asrc = (seg == 0) ? A0 : A1;
    const float* b = Asrc + (size_t)row * C + k0;
    p[0] = *(const float4*)(b);
    p[1] = *(const float4*)(b + 4);
    p[2] = *(const float4*)(b + 8);
    p[3] = *(const float4*)(b + 12);
    if (MODE == 2 && seg == 1) {
        const float* gb = A2 + (size_t)row * C + k0;
        float4 g0 = *(const float4*)(gb);
        float4 g1 = *(const float4*)(gb + 4);
        float4 g2 = *(const float4*)(gb + 8);
        float4 g3 = *(const float4*)(gb + 12);
        p[0].x *= g0.x; p[0].y *= g0.y; p[0].z *= g0.z; p[0].w *= g0.w;
        p[1].x *= g1.x; p[1].y *= g1.y; p[1].z *= g1.z; p[1].w *= g1.w;
        p[2].x *= g2.x; p[2].y *= g2.y; p[2].z *= g2.z; p[2].w *= g2.w;
        p[3].x *= g3.x; p[3].y *= g3.y; p[3].z *= g3.z; p[3].w *= g3.w;
    }
}

template <int MODE>
__global__ void __launch_bounds__(256) gemm_kernel(
    const float* __restrict__ A0, const float* __restrict__ A1,
    const float* __restrict__ A2, const float* __restrict__ W,
    float* __restrict__ out, int N)
{
    __shared__ float Ws[C * C];       // 36 KB: one 96x96 W segment
    const int NSEG = (MODE == 0) ? 1 : 2;
    const int tid  = threadIdx.x;
    const int lane = tid & 31;
    const int wid  = tid >> 5;
    const int g    = lane & 7;
    const int s    = lane >> 3;
    const int row  = (blockIdx.x * 8 + wid) * 4 + s;
    const bool valid = (row < N);

    float acc[12];
    #pragma unroll
    for (int c = 0; c < 12; c++) acc[c] = 0.0f;

    float4 p[4];
    gemm_load_chunk<MODE>(A0, A1, A2, 0, row, 0, valid, p);

    for (int seg = 0; seg < NSEG; seg++) {
        if (seg > 0) __syncthreads();           // protect Ws reuse
        const float* wseg = W + (size_t)seg * C * C;
        for (int i = tid * 4; i < C * C; i += 256 * 4)
            *(float4*)&Ws[i] = *(const float4*)&wseg[i];
        __syncthreads();

        #pragma unroll 1
        for (int t = 0; t < 6; t++) {
            // issue next chunk's loads before consuming current
            float4 q[4];
            {
                int tn = t + 1;
                int segn = seg, k0n = tn * 16;
                if (tn == 6) { segn = seg + 1; k0n = 0; }
                if (segn < NSEG)
                    gemm_load_chunk<MODE>(A0, A1, A2, segn, row, k0n, valid, q);
                else
                    q[0] = q[1] = q[2] = q[3] = make_float4(0.f, 0.f, 0.f, 0.f);
            }

            const float* wbase = &Ws[(t * 16) * C + g * 12];
            float a[16];
            a[0]=p[0].x; a[1]=p[0].y; a[2]=p[0].z; a[3]=p[0].w;
            a[4]=p[1].x; a[5]=p[1].y; a[6]=p[1].z; a[7]=p[1].w;
            a[8]=p[2].x; a[9]=p[2].y; a[10]=p[2].z; a[11]=p[2].w;
            a[12]=p[3].x; a[13]=p[3].y; a[14]=p[3].z; a[15]=p[3].w;
            #pragma unroll
            for (int kk = 0; kk < 16; kk++) {
                const float* wr = wbase + kk * C;
                float4 w0 = *(const float4*)(wr);
                float4 w1 = *(const float4*)(wr + 4);
                float4 w2 = *(const float4*)(wr + 8);
                float av = a[kk];
                acc[0]  += av * w0.x; acc[1]  += av * w0.y;
                acc[2]  += av * w0.z; acc[3]  += av * w0.w;
                acc[4]  += av * w1.x; acc[5]  += av * w1.y;
                acc[6]  += av * w1.z; acc[7]  += av * w1.w;
                acc[8]  += av * w2.x; acc[9]  += av * w2.y;
                acc[10] += av * w2.z; acc[11] += av * w2.w;
            }
            p[0] = q[0]; p[1] = q[1]; p[2] = q[2]; p[3] = q[3];
        }
    }

    if (valid) {
        float* o = out + (size_t)row * C + g * 12;
        *(float4*)(o)     = make_float4(acc[0], acc[1], acc[2],  acc[3]);
        *(float4*)(o + 4) = make_float4(acc[4], acc[5], acc[6],  acc[7]);
        *(float4*)(o + 8) = make_float4(acc[8], acc[9], acc[10], acc[11]);
    }
}

// ---------------- CSR gather aggregation v3 (measured fast) ----------------
// 3 warps per node: warp = (node, channel-third); lane owns channel third*32+lane.
template <int MODE>
__global__ void __launch_bounds__(256) agg_kernel(
    const float* __restrict__ H,
    const float* __restrict__ bias,
    const float* __restrict__ G,
    const float* __restrict__ HP,
    float* __restrict__ out, int N)
{
    __shared__ int2 cs[8][32];
    const int wid  = threadIdx.x >> 5;
    const int lane = threadIdx.x & 31;
    const int gw   = blockIdx.x * 8 + wid;
    const int n     = gw / 3;
    const int third = gw - n * 3;
    if (n >= N) return;
    const int c = third * 32 + lane;

    float dn = d_dinv[n];
    float a = bias[c] + dn * dn * H[(size_t)n * C + c];

    const int jbeg = d_rowptr[n];
    const int jend = d_rowptr[n + 1];

    for (int base = jbeg; base < jend; base += 32) {
        int cnt = jend - base;
        if (cnt > 32) cnt = 32;
        if (lane < cnt) cs[wid][lane] = d_csr[base + lane];
        __syncwarp();
        int t = 0;
        for (; t + 8 <= cnt; t += 8) {
            float xv[8], wv[8];
            #pragma unroll
            for (int q = 0; q < 8; q++) {
                int2 e = cs[wid][t + q];
                wv[q] = __int_as_float(e.y);
                xv[q] = H[(size_t)e.x * C + c];
            }
            #pragma unroll
            for (int q = 0; q < 8; q++) a += wv[q] * xv[q];
        }
        for (; t < cnt; t++) {
            int2 e = cs[wid][t];
            a += __int_as_float(e.y) * H[(size_t)e.x * C + c];
        }
        __syncwarp();
    }

    const size_t o = (size_t)n * C + c;
    if (MODE == 0) {
        out[o] = a;
    } else if (MODE == 1) {
        out[o] = fsigmoid(a);
    } else {
        float u = G[o];
        out[o] = u * HP[o] + (1.0f - u) * ftanh(a);
    }
}

// ---------------- launch ----------------
// NOTE: launch index 3 is a FULL-SIZE dummy gemm<1> on (x, h_prev) — the ncu
// capture window profiles my 4th launch, so this measures the dominant GEMM
// shape. Deterministic (inputs are call-constant); writes d_h1 which
// gemm<0> fully overwrites before any consumer reads it.
extern "C" void kernel_launch(void* const* d_in, const int* in_sizes, int n_in,
                              void* d_out, int out_size)
{
    const float* x      = (const float*)d_in[0];
    const void*  ei     = d_in[1];
    const float* h_prev = (const float*)d_in[2];
    const float* Wx     = (const float*)d_in[3];
    const float* bx     = (const float*)d_in[4];
    const float* Wuh    = (const float*)d_in[5];
    const float* buh    = (const float*)d_in[6];
    const float* Wch    = (const float*)d_in[7];
    const float* bch    = (const float*)d_in[8];
    float*       out    = (float*)d_out;

    int N = in_sizes[0] / C;
    int E = in_sizes[1] / 2;
    if (N > NMAX) N = NMAX;
    if (E > EMAX) E = EMAX;

    const int TB = 256;
    int nb_nodes = (N + TB - 1) / TB;
    int nb_edges = (E + TB - 1) / TB;
    int nb_scan  = (N + SCAN_TPB - 1) / SCAN_TPB;
    int nb_gemm  = (N + 31) / 32;                  // 32 rows per block
    int nb_agg   = (N * 3 + 7) / 8;                // 3 warps/node, 8 warps/block

    // launches 0-2: CSR prologue
    detect_kernel<<<1, 256>>>((const int*)ei, E);
    zero_deg_kernel<<<nb_nodes, TB>>>(N);
    hist_kernel<<<nb_edges, TB>>>(ei, E, N);

    // launch 3: dummy gemm<1> (profiling target)
    gemm_kernel<1><<<nb_gemm, 256>>>(x, h_prev, nullptr, Wuh, d_h1, N);

    // CSR build
    scan_partial_kernel<<<nb_scan, SCAN_TPB>>>(N);
    scan_mid_kernel<<<1, 256>>>(nb_scan, N);
    scan_final_kernel<<<nb_scan, SCAN_TPB>>>(N);
    fill_kernel<<<nb_edges, TB>>>(ei, E, N);

    // GCN 1
    gemm_kernel<0><<<nb_gemm, 256>>>(x, nullptr, nullptr, Wx, d_h1, N);
    agg_kernel<0><<<nb_agg, TB>>>(d_h1, bx, nullptr, nullptr, d_xgcn, N);

    // GCN 2
    gemm_kernel<1><<<nb_gemm, 256>>>(d_xgcn, h_prev, nullptr, Wuh, d_h1, N);
    agg_kernel<1><<<nb_agg, TB>>>(d_h1, buh, nullptr, nullptr, d_g, N);

    // GCN 3 + GRU epilogue
    gemm_kernel<2><<<nb_gemm, 256>>>(d_xgcn, h_prev, d_g, Wch, d_h1, N);
    agg_kernel<2><<<nb_agg, TB>>>(d_h1, bch, d_g, h_prev, out, N);
}

// round 7
// speedup vs baseline: 13.2301x; 12.7283x over previous
#include <cuda_runtime.h>

// ---------------- problem constants ----------------
#define C 96                 // feature channels (d = h = 96)
#define NMAX 65536
#define EMAX 1048576

// ---------------- device scratch (no allocations allowed) ----------------
__device__ int   d_is64;
__device__ int   d_deg[NMAX];
__device__ int   d_rowptr[NMAX + 1];
__device__ int   d_cursor[NMAX];
__device__ int   d_bsum[1024];
__device__ int   d_boff[1024];
__device__ int2  d_csr[EMAX];
__device__ float d_dinv[NMAX];
__device__ float d_h1[(size_t)NMAX * C];
__device__ float d_xgcn[(size_t)NMAX * C];
__device__ float d_g[(size_t)NMAX * C];

// grid-barrier state (monotonic generation; survives across graph replays)
__device__ unsigned          d_barcnt = 0;
__device__ volatile unsigned d_bargen = 0;

// ---------------- helpers ----------------
__device__ __forceinline__ float fsigmoid(float x) {
    return 1.0f / (1.0f + __expf(-x));
}
__device__ __forceinline__ float ftanh(float x) {
    return 1.0f - 2.0f / (__expf(2.0f * x) + 1.0f);
}
__device__ __forceinline__ int load_idx(const void* ei, int idx, int is64) {
    if (is64) return (int)((const long long*)ei)[idx];
    return ((const int*)ei)[idx];
}

// Software grid barrier. All blocks must be co-resident (grid sized via
// occupancy API). Release: every thread fences (drains its global writes),
// then one arrival atomic per block. Acquire: fence after the spin emits
// CCTL.IVALL on sm_103a -> post-barrier loads can't hit stale L1.
__device__ __forceinline__ void grid_barrier() {
    __threadfence();
    __syncthreads();
    if (threadIdx.x == 0) {
        unsigned g = d_bargen;
        unsigned t = atomicAdd(&d_barcnt, 1u);
        if (t == gridDim.x - 1) {
            atomicExch(&d_barcnt, 0u);
            __threadfence();
            d_bargen = g + 1;
        } else {
            while (d_bargen == g) __nanosleep(64);
        }
    }
    __syncthreads();
    __threadfence();
}

// ---------------- GEMM phase (device function) ----------------
// out[N,96] = A[N,K] @ W[K,96]
// MODE 0: K=96, A=A0.  MODE 1: K=192, A=[A0,A1].  MODE 2: K=192, A=[A0,A1.*A2].
// W fully staged in smem; warp owns 4 rows x 96 cols; lane (g=lane&7,s=lane>>3)
// holds acc[12] for row (tile*32 + wid*4 + s), cols g*12..+11.
template <int MODE>
__device__ __forceinline__ void gemm_load_chunk(
    const float* __restrict__ A0, const float* __restrict__ A1,
    const float* __restrict__ A2, int seg, int row, int k0, bool valid,
    float4* p)
{
    if (!valid) {
        p[0] = p[1] = p[2] = p[3] = make_float4(0.f, 0.f, 0.f, 0.f);
        return;
    }
    const float* Asrc = (seg == 0) ? A0 : A1;
    const float* b = Asrc + (size_t)row * C + k0;
    p[0] = *(const float4*)(b);
    p[1] = *(const float4*)(b + 4);
    p[2] = *(const float4*)(b + 8);
    p[3] = *(const float4*)(b + 12);
    if (MODE == 2 && seg == 1) {
        const float* gb = A2 + (size_t)row * C + k0;
        float4 g0 = *(const float4*)(gb);
        float4 g1 = *(const float4*)(gb + 4);
        float4 g2 = *(const float4*)(gb + 8);
        float4 g3 = *(const float4*)(gb + 12);
        p[0].x *= g0.x; p[0].y *= g0.y; p[0].z *= g0.z; p[0].w *= g0.w;
        p[1].x *= g1.x; p[1].y *= g1.y; p[1].z *= g1.z; p[1].w *= g1.w;
        p[2].x *= g2.x; p[2].y *= g2.y; p[2].z *= g2.z; p[2].w *= g2.w;
        p[3].x *= g3.x; p[3].y *= g3.y; p[3].z *= g3.z; p[3].w *= g3.w;
    }
}

template <int MODE>
__device__ void gemm_phase(
    const float* __restrict__ A0, const float* __restrict__ A1,
    const float* __restrict__ A2, const float* __restrict__ W,
    float* __restrict__ outp, int N, float* sW)
{
    const int NSEG = (MODE == 0) ? 1 : 2;
    const int tid  = threadIdx.x;

    // stage W (whole K x 96)
    const int tot = NSEG * C * C;
    for (int i = tid * 4; i < tot; i += 256 * 4)
        *(float4*)&sW[i] = *(const float4*)&W[i];
    __syncthreads();

    const int lane = tid & 31;
    const int wid  = tid >> 5;
    const int g    = lane & 7;
    const int s    = lane >> 3;
    const int ntile = (N + 31) / 32;
    const int T = NSEG * 6;

    for (int tile = blockIdx.x; tile < ntile; tile += gridDim.x) {
        const int row = tile * 32 + wid * 4 + s;
        const bool valid = row < N;

        float acc[12];
        #pragma unroll
        for (int c2 = 0; c2 < 12; c2++) acc[c2] = 0.0f;

        float4 p[4];
        gemm_load_chunk<MODE>(A0, A1, A2, 0, row, 0, valid, p);

        #pragma unroll 1
        for (int u = 0; u < T; u++) {
            const int seg = (u >= 6) ? 1 : 0;
            const int k0  = (u - seg * 6) * 16;

            float4 q[4];
            if (u + 1 < T) {
                const int un = u + 1;
                const int segn = (un >= 6) ? 1 : 0;
                const int k0n  = (un - segn * 6) * 16;
                gemm_load_chunk<MODE>(A0, A1, A2, segn, row, k0n, valid, q);
            } else {
                q[0] = q[1] = q[2] = q[3] = make_float4(0.f, 0.f, 0.f, 0.f);
            }

            float a[16];
            a[0]=p[0].x;  a[1]=p[0].y;  a[2]=p[0].z;  a[3]=p[0].w;
            a[4]=p[1].x;  a[5]=p[1].y;  a[6]=p[1].z;  a[7]=p[1].w;
            a[8]=p[2].x;  a[9]=p[2].y;  a[10]=p[2].z; a[11]=p[2].w;
            a[12]=p[3].x; a[13]=p[3].y; a[14]=p[3].z; a[15]=p[3].w;

            const float* wbase = &sW[(seg * C + k0) * C + g * 12];
            #pragma unroll
            for (int kk = 0; kk < 16; kk++) {
                const float* wr = wbase + kk * C;
                float4 w0 = *(const float4*)(wr);
                float4 w1 = *(const float4*)(wr + 4);
                float4 w2 = *(const float4*)(wr + 8);
                float av = a[kk];
                acc[0]  += av * w0.x; acc[1]  += av * w0.y;
                acc[2]  += av * w0.z; acc[3]  += av * w0.w;
                acc[4]  += av * w1.x; acc[5]  += av * w1.y;
                acc[6]  += av * w1.z; acc[7]  += av * w1.w;
                acc[8]  += av * w2.x; acc[9]  += av * w2.y;
                acc[10] += av * w2.z; acc[11] += av * w2.w;
            }
            p[0] = q[0]; p[1] = q[1]; p[2] = q[2]; p[3] = q[3];
        }

        if (valid) {
            float* o = outp + (size_t)row * C + g * 12;
            *(float4*)(o)     = make_float4(acc[0], acc[1], acc[2],  acc[3]);
            *(float4*)(o + 4) = make_float4(acc[4], acc[5], acc[6],  acc[7]);
            *(float4*)(o + 8) = make_float4(acc[8], acc[9], acc[10], acc[11]);
        }
    }
}

// ---------------- aggregation phase (device function) ----------------
// task = (node, channel-third); lane owns channel third*32+lane.
template <int MODE>
__device__ void agg_phase(
    const float* __restrict__ H, const float* __restrict__ bias,
    const float* __restrict__ G, const float* __restrict__ HP,
    float* __restrict__ outp, int N, int2* sCS)
{
    const int wid  = threadIdx.x >> 5;
    const int lane = threadIdx.x & 31;
    int2* cs = &sCS[wid * 32];
    const int ntask = 3 * N;

    for (int task = blockIdx.x * 8 + wid; task < ntask; task += gridDim.x * 8) {
        const int n     = task / 3;
        const int third = task - n * 3;
        const int c     = third * 32 + lane;

        float dn = d_dinv[n];
        float a  = bias[c] + dn * dn * H[(size_t)n * C + c];

        const int jbeg = d_rowptr[n];
        const int jend = d_rowptr[n + 1];

        for (int base = jbeg; base < jend; base += 32) {
            int cnt = jend - base;
            if (cnt > 32) cnt = 32;
            if (lane < cnt) cs[lane] = d_csr[base + lane];
            __syncwarp();
            int t = 0;
            for (; t + 8 <= cnt; t += 8) {
                float xv[8], wv[8];
                #pragma unroll
                for (int q = 0; q < 8; q++) {
                    int2 e = cs[t + q];
                    wv[q] = __int_as_float(e.y);
                    xv[q] = H[(size_t)e.x * C + c];
                }
                #pragma unroll
                for (int q = 0; q < 8; q++) a += wv[q] * xv[q];
            }
            for (; t < cnt; t++) {
                int2 e = cs[t];
                a += __int_as_float(e.y) * H[(size_t)e.x * C + c];
            }
            __syncwarp();
        }

        const size_t o = (size_t)n * C + c;
        if (MODE == 0) {
            outp[o] = a;
        } else if (MODE == 1) {
            outp[o] = fsigmoid(a);
        } else {
            float u = G[o];
            outp[o] = u * HP[o] + (1.0f - u) * ftanh(a);
        }
    }
}

// ---------------- the megakernel: entire pipeline, one launch ----------------
__global__ void __launch_bounds__(256) mega_kernel(
    const float* __restrict__ x, const void* __restrict__ ei,
    const float* __restrict__ h_prev,
    const float* __restrict__ Wx,  const float* __restrict__ bx,
    const float* __restrict__ Wuh, const float* __restrict__ buh,
    const float* __restrict__ Wch, const float* __restrict__ bch,
    float* __restrict__ out, int N, int E)
{
    extern __shared__ float sW[];                 // [2*C*C] floats
    int2* sCS = (int2*)(sW + 2 * C * C);          // [8*32] int2 (2 KB)
    int*  sSc = (int*)sCS;                        // scan scratch (reused)

    const int tid  = threadIdx.x;
    const int NB   = gridDim.x;
    const int gtid = blockIdx.x * 256 + tid;
    const int nthr = NB * 256;
    const int lane = tid & 31;
    const int wid  = tid >> 5;

    // ---- P0: zero deg (all blocks) + dtype detect (block 0) ----
    for (int i = gtid; i < N; i += nthr) d_deg[i] = 0;
    if (blockIdx.x == 0) {
        int lim = 2 * E; if (lim > 8192) lim = 8192;
        int nz = 0;
        const int* e32 = (const int*)ei;
        for (int i = 1 + 2 * tid; i < lim; i += 512) nz |= e32[i];
        #pragma unroll
        for (int off = 16; off > 0; off >>= 1)
            nz |= __shfl_xor_sync(0xffffffffu, nz, off);
        if (lane == 0) sSc[wid] = nz;
        __syncthreads();
        if (tid == 0) {
            int r = 0;
            #pragma unroll
            for (int w = 0; w < 8; w++) r |= sSc[w];
            d_is64 = (r == 0) ? 1 : 0;
        }
    }
    grid_barrier();

    const int is64 = d_is64;

    // ---- P1: degree histogram ----
    for (int e = gtid; e < E; e += nthr) {
        int d = load_idx(ei, E + e, is64);
        if ((unsigned)d < (unsigned)N) atomicAdd(&d_deg[d], 1);
    }
    grid_barrier();

    // ---- P2: per-tile (256 nodes) local scan + dinv ----
    const int ntiles = (N + 255) / 256;
    for (int tile = blockIdx.x; tile < ntiles; tile += NB) {
        int i = tile * 256 + tid;
        int v = (i < N) ? d_deg[i] : 0;
        if (i < N) d_dinv[i] = rsqrtf((float)v + 1.0f);
        int xv = v;
        #pragma unroll
        for (int off = 1; off < 32; off <<= 1) {
            int y = __shfl_up_sync(0xffffffffu, xv, off);
            if (lane >= off) xv += y;
        }
        if (lane == 31) sSc[wid] = xv;
        __syncthreads();
        if (wid == 0 && lane < 8) {
            int s2 = sSc[lane];
            #pragma unroll
            for (int off = 1; off < 8; off <<= 1) {
                int y = __shfl_up_sync(0xffu, s2, off);
                if (lane >= off) s2 += y;
            }
            sSc[lane] = s2;
        }
        __syncthreads();
        int incl = xv + ((wid > 0) ? sSc[wid - 1] : 0);
        if (i < N) d_rowptr[i] = incl - v;        // local exclusive
        if (tid == 255) d_bsum[tile] = incl;      // tile total
        __syncthreads();                          // protect sSc next iter
    }
    grid_barrier();

    // ---- P3: block 0 scans tile totals ----
    if (blockIdx.x == 0) {
        int carry = 0;
        for (int base = 0; base < ntiles; base += 256) {
            int t2 = base + tid;
            int v = (t2 < ntiles) ? d_bsum[t2] : 0;
            int xv = v;
            #pragma unroll
            for (int off = 1; off < 32; off <<= 1) {
                int y = __shfl_up_sync(0xffffffffu, xv, off);
                if (lane >= off) xv += y;
            }
            if (lane == 31) sSc[wid] = xv;
            __syncthreads();
            if (wid == 0 && lane < 8) {
                int s2 = sSc[lane];
                #pragma unroll
                for (int off = 1; off < 8; off <<= 1) {
                    int y = __shfl_up_sync(0xffu, s2, off);
                    if (lane >= off) s2 += y;
                }
                sSc[lane] = s2;
            }
            __syncthreads();
            int incl = xv + ((wid > 0) ? sSc[wid - 1] : 0);
            if (t2 < ntiles) d_boff[t2] = carry + incl - v;
            int tot = sSc[7];
            __syncthreads();
            carry += tot;
        }
        if (tid == 0) d_rowptr[N] = carry;
    }
    grid_barrier();

    // ---- P4: apply tile offsets -> rowptr / cursor ----
    for (int tile = blockIdx.x; tile < ntiles; tile += NB) {
        int i = tile * 256 + tid;
        if (i < N) {
            int rp = d_rowptr[i] + d_boff[tile];
            d_rowptr[i] = rp;
            d_cursor[i] = rp;
        }
    }
    grid_barrier();

    // ---- P5: CSR fill ----
    for (int e = gtid; e < E; e += nthr) {
        int s = load_idx(ei, e, is64);
        int d = load_idx(ei, E + e, is64);
        if ((unsigned)s < (unsigned)N && (unsigned)d < (unsigned)N) {
            int p = atomicAdd(&d_cursor[d], 1);
            d_csr[p] = make_int2(s, __float_as_int(d_dinv[s] * d_dinv[d]));
        }
    }
    grid_barrier();

    // ---- P6..P11: 3 x (GEMM + aggregation) ----
    gemm_phase<0>(x, nullptr, nullptr, Wx, d_h1, N, sW);
    grid_barrier();
    agg_phase<0>(d_h1, bx, nullptr, nullptr, d_xgcn, N, sCS);
    grid_barrier();

    gemm_phase<1>(d_xgcn, h_prev, nullptr, Wuh, d_h1, N, sW);
    grid_barrier();
    agg_phase<1>(d_h1, buh, nullptr, nullptr, d_g, N, sCS);
    grid_barrier();

    gemm_phase<2>(d_xgcn, h_prev, d_g, Wch, d_h1, N, sW);
    grid_barrier();
    agg_phase<2>(d_h1, bch, d_g, h_prev, out, N, sCS);
}

// ---------------- launch: ONE kernel ----------------
extern "C" void kernel_launch(void* const* d_in, const int* in_sizes, int n_in,
                              void* d_out, int out_size)
{
    const float* x      = (const float*)d_in[0];
    const void*  ei     = d_in[1];
    const float* h_prev = (const float*)d_in[2];
    const float* Wx     = (const float*)d_in[3];
    const float* bx     = (const float*)d_in[4];
    const float* Wuh    = (const float*)d_in[5];
    const float* buh    = (const float*)d_in[6];
    const float* Wch    = (const float*)d_in[7];
    const float* bch    = (const float*)d_in[8];
    float*       out    = (float*)d_out;

    int N = in_sizes[0] / C;
    int E = in_sizes[1] / 2;
    if (N > NMAX) N = NMAX;
    if (E > EMAX) E = EMAX;

    const int SMEM_BYTES = 2 * C * C * (int)sizeof(float) + 8 * 32 * (int)sizeof(int2);

    cudaFuncSetAttribute(mega_kernel,
                         cudaFuncAttributeMaxDynamicSharedMemorySize, SMEM_BYTES);

    int dev = 0;
    cudaGetDevice(&dev);
    int nsm = 148;
    cudaDeviceGetAttribute(&nsm, cudaDevAttrMultiProcessorCount, dev);
    int occ = 1;
    cudaOccupancyMaxActiveBlocksPerMultiprocessor(&occ, mega_kernel, 256, SMEM_BYTES);
    if (occ < 1) occ = 1;
    int grid = nsm * occ;   // guaranteed co-resident -> grid barrier is safe

    mega_kernel<<<grid, 256, SMEM_BYTES>>>(
        x, ei, h_prev, Wx, bx, Wuh, buh, Wch, bch, out, N, E);
}

// round 8
// speedup vs baseline: 15.1136x; 1.1424x over previous
#include <cuda_runtime.h>

// ---------------- problem constants ----------------
#define C 96                 // feature channels (d = h = 96)
#define NMAX 65536
#define EMAX 1048576

// ---------------- device scratch (no allocations allowed) ----------------
__device__ int   d_is64;
__device__ int   d_deg[NMAX];
__device__ int   d_rowptr[NMAX];       // tile-LOCAL exclusive scan
__device__ int   d_cursor[NMAX];       // tile-LOCAL fill cursor
__device__ int   d_bsum[1024];         // per-tile degree totals
__device__ int   d_boff[1024];         // per-tile global offsets
__device__ int2  d_csr[EMAX];
__device__ float d_dinv[NMAX];
__device__ float d_h1[(size_t)NMAX * C];
__device__ float d_xgcn[(size_t)NMAX * C];
__device__ float d_g[(size_t)NMAX * C];

// grid-barrier state (monotonic generation; survives across graph replays)
__device__ unsigned          d_barcnt = 0;
__device__ volatile unsigned d_bargen = 0;
__device__ unsigned          d_p2done = 0;   // last-block ticket for mid-scan

// ---------------- helpers ----------------
__device__ __forceinline__ float fsigmoid(float x) {
    return 1.0f / (1.0f + __expf(-x));
}
__device__ __forceinline__ float ftanh(float x) {
    return 1.0f - 2.0f / (__expf(2.0f * x) + 1.0f);
}
__device__ __forceinline__ int load_idx(const void* ei, int idx, int is64) {
    if (is64) return (int)((const long long*)ei)[idx];
    return ((const int*)ei)[idx];
}

// Software grid barrier (all blocks co-resident; grid sized via occupancy API).
__device__ __forceinline__ void grid_barrier() {
    __threadfence();
    __syncthreads();
    if (threadIdx.x == 0) {
        unsigned g = d_bargen;
        unsigned t = atomicAdd(&d_barcnt, 1u);
        if (t == gridDim.x - 1) {
            atomicExch(&d_barcnt, 0u);
            __threadfence();
            d_bargen = g + 1;
        } else {
            while (d_bargen == g) __nanosleep(64);
        }
    }
    __syncthreads();
    __threadfence();
}

// ---------------- GEMM phase ----------------
// out[N,96] = A[N,K] @ W[K,96]; K processed in 96-row segments, one staged in
// smem at a time (36 KB). Segment 1 accumulates via out += (same thread owns
// the same output elements in both passes -> plain RAW through memory).
// Warp owns 4 rows x 96 cols: lane (g=lane&7, s=lane>>3) -> acc[12] for
// row (tile*32 + wid*4 + s), cols g*12..+11.
template <int MODE>
__device__ __forceinline__ void gemm_load_chunk(
    const float* __restrict__ A0, const float* __restrict__ A1,
    const float* __restrict__ A2, int seg, int row, int k0, bool valid,
    float4* p)
{
    if (!valid) {
        p[0] = p[1] = p[2] = p[3] = make_float4(0.f, 0.f, 0.f, 0.f);
        return;
    }
    const float* Asrc = (seg == 0) ? A0 : A1;
    const float* b = Asrc + (size_t)row * C + k0;
    p[0] = *(const float4*)(b);
    p[1] = *(const float4*)(b + 4);
    p[2] = *(const float4*)(b + 8);
    p[3] = *(const float4*)(b + 12);
    if (MODE == 2 && seg == 1) {
        const float* gb = A2 + (size_t)row * C + k0;
        float4 g0 = *(const float4*)(gb);
        float4 g1 = *(const float4*)(gb + 4);
        float4 g2 = *(const float4*)(gb + 8);
        float4 g3 = *(const float4*)(gb + 12);
        p[0].x *= g0.x; p[0].y *= g0.y; p[0].z *= g0.z; p[0].w *= g0.w;
        p[1].x *= g1.x; p[1].y *= g1.y; p[1].z *= g1.z; p[1].w *= g1.w;
        p[2].x *= g2.x; p[2].y *= g2.y; p[2].z *= g2.z; p[2].w *= g2.w;
        p[3].x *= g3.x; p[3].y *= g3.y; p[3].z *= g3.z; p[3].w *= g3.w;
    }
}

template <int MODE>
__device__ void gemm_phase(
    const float* __restrict__ A0, const float* __restrict__ A1,
    const float* __restrict__ A2, const float* __restrict__ W,
    float* __restrict__ outp, int N, float* sW)
{
    const int NSEG = (MODE == 0) ? 1 : 2;
    const int tid  = threadIdx.x;
    const int lane = tid & 31;
    const int wid  = tid >> 5;
    const int g    = lane & 7;
    const int s    = lane >> 3;
    const int ntile = (N + 31) / 32;

    for (int seg = 0; seg < NSEG; seg++) {
        __syncthreads();                          // prior users of sW done
        const float* wseg = W + (size_t)seg * C * C;
        for (int i = tid * 4; i < C * C; i += 256 * 4)
            *(float4*)&sW[i] = *(const float4*)&wseg[i];
        __syncthreads();

        for (int tile = blockIdx.x; tile < ntile; tile += gridDim.x) {
            const int row = tile * 32 + wid * 4 + s;
            const bool valid = row < N;

            float acc[12];
            #pragma unroll
            for (int c2 = 0; c2 < 12; c2++) acc[c2] = 0.0f;

            float4 p[4];
            gemm_load_chunk<MODE>(A0, A1, A2, seg, row, 0, valid, p);

            #pragma unroll 1
            for (int t = 0; t < 6; t++) {
                float4 q[4];
                if (t + 1 < 6)
                    gemm_load_chunk<MODE>(A0, A1, A2, seg, row, (t + 1) * 16, valid, q);
                else
                    q[0] = q[1] = q[2] = q[3] = make_float4(0.f, 0.f, 0.f, 0.f);

                float a[16];
                a[0]=p[0].x;  a[1]=p[0].y;  a[2]=p[0].z;  a[3]=p[0].w;
                a[4]=p[1].x;  a[5]=p[1].y;  a[6]=p[1].z;  a[7]=p[1].w;
                a[8]=p[2].x;  a[9]=p[2].y;  a[10]=p[2].z; a[11]=p[2].w;
                a[12]=p[3].x; a[13]=p[3].y; a[14]=p[3].z; a[15]=p[3].w;

                const float* wbase = &sW[(t * 16) * C + g * 12];
                #pragma unroll
                for (int kk = 0; kk < 16; kk++) {
                    const float* wr = wbase + kk * C;
                    float4 w0 = *(const float4*)(wr);
                    float4 w1 = *(const float4*)(wr + 4);
                    float4 w2 = *(const float4*)(wr + 8);
                    float av = a[kk];
                    acc[0]  += av * w0.x; acc[1]  += av * w0.y;
                    acc[2]  += av * w0.z; acc[3]  += av * w0.w;
                    acc[4]  += av * w1.x; acc[5]  += av * w1.y;
                    acc[6]  += av * w1.z; acc[7]  += av * w1.w;
                    acc[8]  += av * w2.x; acc[9]  += av * w2.y;
                    acc[10] += av * w2.z; acc[11] += av * w2.w;
                }
                p[0] = q[0]; p[1] = q[1]; p[2] = q[2]; p[3] = q[3];
            }

            if (valid) {
                float* o = outp + (size_t)row * C + g * 12;
                if (seg == 0) {
                    *(float4*)(o)     = make_float4(acc[0], acc[1], acc[2],  acc[3]);
                    *(float4*)(o + 4) = make_float4(acc[4], acc[5], acc[6],  acc[7]);
                    *(float4*)(o + 8) = make_float4(acc[8], acc[9], acc[10], acc[11]);
                } else {
                    float4 o0 = *(float4*)(o);
                    float4 o1 = *(float4*)(o + 4);
                    float4 o2 = *(float4*)(o + 8);
                    *(float4*)(o)     = make_float4(o0.x + acc[0], o0.y + acc[1],
                                                    o0.z + acc[2], o0.w + acc[3]);
                    *(float4*)(o + 4) = make_float4(o1.x + acc[4], o1.y + acc[5],
                                                    o1.z + acc[6], o1.w + acc[7]);
                    *(float4*)(o + 8) = make_float4(o2.x + acc[8], o2.y + acc[9],
                                                    o2.z + acc[10], o2.w + acc[11]);
                }
            }
        }
    }
}

// ---------------- aggregation phase ----------------
// task = (node, channel-third); lane owns channel third*32+lane.
// Global CSR position = tile-local rowptr + per-tile offset; extent = deg[n].
template <int MODE>
__device__ void agg_phase(
    const float* __restrict__ H, const float* __restrict__ bias,
    const float* __restrict__ G, const float* __restrict__ HP,
    float* __restrict__ outp, int N, int2* sCS)
{
    const int wid  = threadIdx.x >> 5;
    const int lane = threadIdx.x & 31;
    int2* cs = &sCS[wid * 32];
    const int ntask = 3 * N;

    for (int task = blockIdx.x * 8 + wid; task < ntask; task += gridDim.x * 8) {
        const int n     = task / 3;
        const int third = task - n * 3;
        const int c     = third * 32 + lane;

        float dn = d_dinv[n];
        float a  = bias[c] + dn * dn * H[(size_t)n * C + c];

        const int jbeg = d_rowptr[n] + d_boff[n >> 8];
        const int jend = jbeg + d_deg[n];

        for (int base = jbeg; base < jend; base += 32) {
            int cnt = jend - base;
            if (cnt > 32) cnt = 32;
            if (lane < cnt) cs[lane] = d_csr[base + lane];
            __syncwarp();
            int t = 0;
            for (; t + 8 <= cnt; t += 8) {
                float xv[8], wv[8];
                #pragma unroll
                for (int q = 0; q < 8; q++) {
                    int2 e = cs[t + q];
                    wv[q] = __int_as_float(e.y);
                    xv[q] = H[(size_t)e.x * C + c];
                }
                #pragma unroll
                for (int q = 0; q < 8; q++) a += wv[q] * xv[q];
            }
            for (; t < cnt; t++) {
                int2 e = cs[t];
                a += __int_as_float(e.y) * H[(size_t)e.x * C + c];
            }
            __syncwarp();
        }

        const size_t o = (size_t)n * C + c;
        if (MODE == 0) {
            outp[o] = a;
        } else if (MODE == 1) {
            outp[o] = fsigmoid(a);
        } else {
            float u = G[o];
            outp[o] = u * HP[o] + (1.0f - u) * ftanh(a);
        }
    }
}

// ---------------- the megakernel ----------------
__global__ void __launch_bounds__(256, 4) mega_kernel(
    const float* __restrict__ x, const void* __restrict__ ei,
    const float* __restrict__ h_prev,
    const float* __restrict__ Wx,  const float* __restrict__ bx,
    const float* __restrict__ Wuh, const float* __restrict__ buh,
    const float* __restrict__ Wch, const float* __restrict__ bch,
    float* __restrict__ out, int N, int E)
{
    extern __shared__ float sW[];                 // [C*C] floats (36 KB)
    int2* sCS = (int2*)(sW + C * C);              // [8*32] int2 (2 KB)
    int*  sSc = (int*)sCS;                        // scan scratch (aliased)

    const int tid  = threadIdx.x;
    const int NB   = gridDim.x;
    const int gtid = blockIdx.x * 256 + tid;
    const int nthr = NB * 256;
    const int lane = tid & 31;
    const int wid  = tid >> 5;

    // ---- Phase A: zero deg + dtype detect (block 0) + gemm<0> ----
    for (int i = gtid; i < N; i += nthr) d_deg[i] = 0;
    if (blockIdx.x == 0) {
        int lim = 2 * E; if (lim > 8192) lim = 8192;
        int nz = 0;
        const int* e32 = (const int*)ei;
        for (int i = 1 + 2 * tid; i < lim; i += 512) nz |= e32[i];
        #pragma unroll
        for (int off = 16; off > 0; off >>= 1)
            nz |= __shfl_xor_sync(0xffffffffu, nz, off);
        if (lane == 0) sSc[wid] = nz;
        __syncthreads();
        if (tid == 0) {
            int r = 0;
            #pragma unroll
            for (int w = 0; w < 8; w++) r |= sSc[w];
            d_is64 = (r == 0) ? 1 : 0;
        }
        __syncthreads();                           // sSc reuse (sCS aliases sW? no)
    }
    gemm_phase<0>(x, nullptr, nullptr, Wx, d_h1, N, sW);
    grid_barrier();                                            // B1

    const int is64 = d_is64;

    // ---- Phase B: degree histogram ----
    for (int e = gtid; e < E; e += nthr) {
        int d = load_idx(ei, E + e, is64);
        if ((unsigned)d < (unsigned)N) atomicAdd(&d_deg[d], 1);
    }
    grid_barrier();                                            // B2

    // ---- Phase C: per-tile local scan + dinv; LAST block does mid-scan ----
    const int ntiles = (N + 255) / 256;
    for (int tile = blockIdx.x; tile < ntiles; tile += NB) {
        int i = tile * 256 + tid;
        int v = (i < N) ? d_deg[i] : 0;
        if (i < N) d_dinv[i] = rsqrtf((float)v + 1.0f);
        int xv = v;
        #pragma unroll
        for (int off = 1; off < 32; off <<= 1) {
            int y = __shfl_up_sync(0xffffffffu, xv, off);
            if (lane >= off) xv += y;
        }
        if (lane == 31) sSc[wid] = xv;
        __syncthreads();
        if (wid == 0 && lane < 8) {
            int s2 = sSc[lane];
            #pragma unroll
            for (int off = 1; off < 8; off <<= 1) {
                int y = __shfl_up_sync(0xffu, s2, off);
                if (lane >= off) s2 += y;
            }
            sSc[lane] = s2;
        }
        __syncthreads();
        int incl = xv + ((wid > 0) ? sSc[wid - 1] : 0);
        if (i < N) {
            int excl = incl - v;
            d_rowptr[i] = excl;                    // tile-local
            d_cursor[i] = excl;
        }
        if (tid == 255) d_bsum[tile] = incl;
        __syncthreads();
    }
    // last-block ticket -> mid-scan of tile totals
    {
        __shared__ int amLast;
        __threadfence();
        __syncthreads();
        if (tid == 0) {
            unsigned t = atomicAdd(&d_p2done, 1u);
            amLast = (t == (unsigned)(NB - 1));
            if (amLast) d_p2done = 0;
        }
        __syncthreads();
        if (amLast) {
            __threadfence();                       // acquire bsum writes
            // ntiles <= 256: single 256-wide scan
            int v = (tid < ntiles) ? d_bsum[tid] : 0;
            int xv = v;
            #pragma unroll
            for (int off = 1; off < 32; off <<= 1) {
                int y = __shfl_up_sync(0xffffffffu, xv, off);
                if (lane >= off) xv += y;
            }
            if (lane == 31) sSc[wid] = xv;
            __syncthreads();
            if (wid == 0 && lane < 8) {
                int s2 = sSc[lane];
                #pragma unroll
                for (int off = 1; off < 8; off <<= 1) {
                    int y = __shfl_up_sync(0xffu, s2, off);
                    if (lane >= off) s2 += y;
                }
                sSc[lane] = s2;
            }
            __syncthreads();
            int incl = xv + ((wid > 0) ? sSc[wid - 1] : 0);
            if (tid < ntiles) d_boff[tid] = incl - v;
        }
    }
    grid_barrier();                                            // B3

    // ---- Phase D: CSR fill (global pos = local cursor + tile offset) ----
    for (int e = gtid; e < E; e += nthr) {
        int s = load_idx(ei, e, is64);
        int d = load_idx(ei, E + e, is64);
        if ((unsigned)s < (unsigned)N && (unsigned)d < (unsigned)N) {
            int p = atomicAdd(&d_cursor[d], 1) + d_boff[d >> 8];
            d_csr[p] = make_int2(s, __float_as_int(d_dinv[s] * d_dinv[d]));
        }
    }
    grid_barrier();                                            // B4

    // ---- Phases E..I: agg0, gemm1, agg1, gemm2, agg2 ----
    agg_phase<0>(d_h1, bx, nullptr, nullptr, d_xgcn, N, sCS);
    grid_barrier();                                            // B5

    gemm_phase<1>(d_xgcn, h_prev, nullptr, Wuh, d_h1, N, sW);
    grid_barrier();                                            // B6

    agg_phase<1>(d_h1, buh, nullptr, nullptr, d_g, N, sCS);
    grid_barrier();                                            // B7

    gemm_phase<2>(d_xgcn, h_prev, d_g, Wch, d_h1, N, sW);
    grid_barrier();                                            // B8

    agg_phase<2>(d_h1, bch, d_g, h_prev, out, N, sCS);
}

// ---------------- launch: ONE kernel ----------------
extern "C" void kernel_launch(void* const* d_in, const int* in_sizes, int n_in,
                              void* d_out, int out_size)
{
    const float* x      = (const float*)d_in[0];
    const void*  ei     = d_in[1];
    const float* h_prev = (const float*)d_in[2];
    const float* Wx     = (const float*)d_in[3];
    const float* bx     = (const float*)d_in[4];
    const float* Wuh    = (const float*)d_in[5];
    const float* buh    = (const float*)d_in[6];
    const float* Wch    = (const float*)d_in[7];
    const float* bch    = (const float*)d_in[8];
    float*       out    = (float*)d_out;

    int N = in_sizes[0] / C;
    int E = in_sizes[1] / 2;
    if (N > NMAX) N = NMAX;
    if (E > EMAX) E = EMAX;

    const int SMEM_BYTES = C * C * (int)sizeof(float) + 8 * 32 * (int)sizeof(int2);

    cudaFuncSetAttribute(mega_kernel,
                         cudaFuncAttributeMaxDynamicSharedMemorySize, SMEM_BYTES);

    int dev = 0;
    cudaGetDevice(&dev);
    int nsm = 148;
    cudaDeviceGetAttribute(&nsm, cudaDevAttrMultiProcessorCount, dev);
    int occ = 1;
    cudaOccupancyMaxActiveBlocksPerMultiprocessor(&occ, mega_kernel, 256, SMEM_BYTES);
    if (occ < 1) occ = 1;
    int grid = nsm * occ;   // guaranteed co-resident -> grid barrier is safe

    mega_kernel<<<grid, 256, SMEM_BYTES>>>(
        x, ei, h_prev, Wx, bx, Wuh, buh, Wch, bch, out, N, E);
}

// round 9
// speedup vs baseline: 19.0792x; 1.2624x over previous
#include <cuda_runtime.h>

// ---------------- problem constants ----------------
#define C 96                 // feature channels (d = h = 96)
#define NMAX 65536
#define EMAX 1048576

// ---------------- device scratch (no allocations allowed) ----------------
__device__ int   d_is64;
__device__ int   d_deg[NMAX];
__device__ int   d_rowptr[NMAX];       // tile-LOCAL exclusive scan
__device__ int   d_cursor[NMAX];       // tile-LOCAL fill cursor
__device__ int   d_bsum[1024];         // per-tile degree totals
__device__ int   d_boff[1024];         // per-tile global offsets
__device__ int2  d_csr[EMAX];
__device__ float d_dinv[NMAX];
__device__ float d_h1[(size_t)NMAX * C];
__device__ float d_xgcn[(size_t)NMAX * C];
__device__ float d_g[(size_t)NMAX * C];

// grid-barrier state (monotonic generation; survives across graph replays)
__device__ unsigned          d_barcnt = 0;
__device__ volatile unsigned d_bargen = 0;
__device__ unsigned          d_p2done = 0;   // last-block ticket for mid-scan

// ---------------- helpers ----------------
__device__ __forceinline__ float fsigmoid(float x) {
    return 1.0f / (1.0f + __expf(-x));
}
__device__ __forceinline__ float ftanh(float x) {
    return 1.0f - 2.0f / (__expf(2.0f * x) + 1.0f);
}
__device__ __forceinline__ int load_idx(const void* ei, int idx, int is64) {
    if (is64) return (int)((const long long*)ei)[idx];
    return ((const int*)ei)[idx];
}

// Software grid barrier (all blocks co-resident; grid sized via occupancy API).
__device__ __forceinline__ void grid_barrier() {
    __threadfence();
    __syncthreads();
    if (threadIdx.x == 0) {
        unsigned g = d_bargen;
        unsigned t = atomicAdd(&d_barcnt, 1u);
        if (t == gridDim.x - 1) {
            atomicExch(&d_barcnt, 0u);
            __threadfence();
            d_bargen = g + 1;
        } else {
            while (d_bargen == g) __nanosleep(64);
        }
    }
    __syncthreads();
    __threadfence();
}

// ---------------- GEMM phase v4: 2 rows/thread, LDS-halved ----------------
// out[N,96] = A[N,K] @ W[K,96]; K in 96-row segments, one staged in smem.
// Segment 1 accumulates via out += (same thread owns the same elements).
// Warp owns 8 rows x 96 cols: lane (g=lane&7, s=lane>>3) holds acc[2][12]
// for rows (tile*64 + wid*8 + s*2 +{0,1}), cols g*12..+11.
// Per 8-k chunk: 4 LDG.128 (A), inner 8x(3 LDS.128 W -> 24 FMA).
template <int MODE>
__device__ __forceinline__ void gemm_load_row8(
    const float* __restrict__ Asrc, const float* __restrict__ A2,
    int seg, int row, int k0, bool valid, float4* p)
{
    if (!valid) {
        p[0] = p[1] = make_float4(0.f, 0.f, 0.f, 0.f);
        return;
    }
    const float* b = Asrc + (size_t)row * C + k0;
    p[0] = *(const float4*)(b);
    p[1] = *(const float4*)(b + 4);
    if (MODE == 2 && seg == 1) {
        const float* gb = A2 + (size_t)row * C + k0;
        float4 g0 = *(const float4*)(gb);
        float4 g1 = *(const float4*)(gb + 4);
        p[0].x *= g0.x; p[0].y *= g0.y; p[0].z *= g0.z; p[0].w *= g0.w;
        p[1].x *= g1.x; p[1].y *= g1.y; p[1].z *= g1.z; p[1].w *= g1.w;
    }
}

template <int MODE>
__device__ void gemm_phase(
    const float* __restrict__ A0, const float* __restrict__ A1,
    const float* __restrict__ A2, const float* __restrict__ W,
    float* __restrict__ outp, int N, float* sW)
{
    const int NSEG = (MODE == 0) ? 1 : 2;
    const int tid  = threadIdx.x;
    const int lane = tid & 31;
    const int wid  = tid >> 5;
    const int g    = lane & 7;
    const int s    = lane >> 3;
    const int ntile = (N + 63) / 64;

    for (int seg = 0; seg < NSEG; seg++) {
        __syncthreads();                          // prior users of sW done
        const float* wseg = W + (size_t)seg * C * C;
        for (int i = tid * 4; i < C * C; i += 256 * 4)
            *(float4*)&sW[i] = *(const float4*)&wseg[i];
        __syncthreads();

        const float* Asrc = (seg == 0) ? A0 : A1;

        for (int tile = blockIdx.x; tile < ntile; tile += gridDim.x) {
            const int row0 = tile * 64 + wid * 8 + s * 2;
            const int row1 = row0 + 1;
            const bool v0 = row0 < N;
            const bool v1 = row1 < N;

            float acc0[12], acc1[12];
            #pragma unroll
            for (int c2 = 0; c2 < 12; c2++) { acc0[c2] = 0.0f; acc1[c2] = 0.0f; }

            #pragma unroll 1
            for (int ch = 0; ch < 12; ch++) {     // 8-k chunks
                const int k0 = ch * 8;
                float4 p0[2], p1[2];
                gemm_load_row8<MODE>(Asrc, A2, seg, row0, k0, v0, p0);
                gemm_load_row8<MODE>(Asrc, A2, seg, row1, k0, v1, p1);

                float a0[8], a1[8];
                a0[0]=p0[0].x; a0[1]=p0[0].y; a0[2]=p0[0].z; a0[3]=p0[0].w;
                a0[4]=p0[1].x; a0[5]=p0[1].y; a0[6]=p0[1].z; a0[7]=p0[1].w;
                a1[0]=p1[0].x; a1[1]=p1[0].y; a1[2]=p1[0].z; a1[3]=p1[0].w;
                a1[4]=p1[1].x; a1[5]=p1[1].y; a1[6]=p1[1].z; a1[7]=p1[1].w;

                const float* wbase = &sW[k0 * C + g * 12];
                #pragma unroll
                for (int kk = 0; kk < 8; kk++) {
                    const float* wr = wbase + kk * C;
                    float4 w0 = *(const float4*)(wr);
                    float4 w1 = *(const float4*)(wr + 4);
                    float4 w2 = *(const float4*)(wr + 8);
                    float av0 = a0[kk], av1 = a1[kk];
                    acc0[0]  += av0 * w0.x; acc0[1]  += av0 * w0.y;
                    acc0[2]  += av0 * w0.z; acc0[3]  += av0 * w0.w;
                    acc0[4]  += av0 * w1.x; acc0[5]  += av0 * w1.y;
                    acc0[6]  += av0 * w1.z; acc0[7]  += av0 * w1.w;
                    acc0[8]  += av0 * w2.x; acc0[9]  += av0 * w2.y;
                    acc0[10] += av0 * w2.z; acc0[11] += av0 * w2.w;
                    acc1[0]  += av1 * w0.x; acc1[1]  += av1 * w0.y;
                    acc1[2]  += av1 * w0.z; acc1[3]  += av1 * w0.w;
                    acc1[4]  += av1 * w1.x; acc1[5]  += av1 * w1.y;
                    acc1[6]  += av1 * w1.z; acc1[7]  += av1 * w1.w;
                    acc1[8]  += av1 * w2.x; acc1[9]  += av1 * w2.y;
                    acc1[10] += av1 * w2.z; acc1[11] += av1 * w2.w;
                }
            }

            #pragma unroll
            for (int r = 0; r < 2; r++) {
                const int   row = r ? row1 : row0;
                const float* ac = r ? acc1 : acc0;
                if (row < N) {
                    float* o = outp + (size_t)row * C + g * 12;
                    if (seg == 0) {
                        *(float4*)(o)     = make_float4(ac[0], ac[1], ac[2],  ac[3]);
                        *(float4*)(o + 4) = make_float4(ac[4], ac[5], ac[6],  ac[7]);
                        *(float4*)(o + 8) = make_float4(ac[8], ac[9], ac[10], ac[11]);
                    } else {
                        float4 o0 = *(float4*)(o);
                        float4 o1 = *(float4*)(o + 4);
                        float4 o2 = *(float4*)(o + 8);
                        *(float4*)(o)     = make_float4(o0.x + ac[0], o0.y + ac[1],
                                                        o0.z + ac[2], o0.w + ac[3]);
                        *(float4*)(o + 4) = make_float4(o1.x + ac[4], o1.y + ac[5],
                                                        o1.z + ac[6], o1.w + ac[7]);
                        *(float4*)(o + 8) = make_float4(o2.x + ac[8], o2.y + ac[9],
                                                        o2.z + ac[10], o2.w + ac[11]);
                    }
                }
            }
        }
    }
}

// ---------------- aggregation phase ----------------
// task = (node, channel-third); lane owns channel third*32+lane.
// Global CSR position = tile-local rowptr + per-tile offset; extent = deg[n].
template <int MODE>
__device__ void agg_phase(
    const float* __restrict__ H, const float* __restrict__ bias,
    const float* __restrict__ G, const float* __restrict__ HP,
    float* __restrict__ outp, int N, int2* sCS)
{
    const int wid  = threadIdx.x >> 5;
    const int lane = threadIdx.x & 31;
    int2* cs = &sCS[wid * 32];
    const int ntask = 3 * N;

    for (int task = blockIdx.x * 8 + wid; task < ntask; task += gridDim.x * 8) {
        const int n     = task / 3;
        const int third = task - n * 3;
        const int c     = third * 32 + lane;

        float dn = d_dinv[n];
        float a  = bias[c] + dn * dn * H[(size_t)n * C + c];

        const int jbeg = d_rowptr[n] + d_boff[n >> 8];
        const int jend = jbeg + d_deg[n];

        for (int base = jbeg; base < jend; base += 32) {
            int cnt = jend - base;
            if (cnt > 32) cnt = 32;
            if (lane < cnt) cs[lane] = d_csr[base + lane];
            __syncwarp();
            int t = 0;
            for (; t + 8 <= cnt; t += 8) {
                float xv[8], wv[8];
                #pragma unroll
                for (int q = 0; q < 8; q++) {
                    int2 e = cs[t + q];
                    wv[q] = __int_as_float(e.y);
                    xv[q] = H[(size_t)e.x * C + c];
                }
                #pragma unroll
                for (int q = 0; q < 8; q++) a += wv[q] * xv[q];
            }
            for (; t < cnt; t++) {
                int2 e = cs[t];
                a += __int_as_float(e.y) * H[(size_t)e.x * C + c];
            }
            __syncwarp();
        }

        const size_t o = (size_t)n * C + c;
        if (MODE == 0) {
            outp[o] = a;
        } else if (MODE == 1) {
            outp[o] = fsigmoid(a);
        } else {
            float u = G[o];
            outp[o] = u * HP[o] + (1.0f - u) * ftanh(a);
        }
    }
}

// ---------------- the megakernel ----------------
__global__ void __launch_bounds__(256, 4) mega_kernel(
    const float* __restrict__ x, const void* __restrict__ ei,
    const float* __restrict__ h_prev,
    const float* __restrict__ Wx,  const float* __restrict__ bx,
    const float* __restrict__ Wuh, const float* __restrict__ buh,
    const float* __restrict__ Wch, const float* __restrict__ bch,
    float* __restrict__ out, int N, int E)
{
    extern __shared__ float sW[];                 // [C*C] floats (36 KB)
    int2* sCS = (int2*)(sW + C * C);              // [8*32] int2 (2 KB)
    int*  sSc = (int*)sCS;                        // scan scratch (aliased)

    const int tid  = threadIdx.x;
    const int NB   = gridDim.x;
    const int gtid = blockIdx.x * 256 + tid;
    const int nthr = NB * 256;
    const int lane = tid & 31;
    const int wid  = tid >> 5;

    // ---- Phase A: zero deg + dtype detect (block 0) + gemm<0> ----
    for (int i = gtid; i < N; i += nthr) d_deg[i] = 0;
    if (blockIdx.x == 0) {
        int lim = 2 * E; if (lim > 8192) lim = 8192;
        int nz = 0;
        const int* e32 = (const int*)ei;
        for (int i = 1 + 2 * tid; i < lim; i += 512) nz |= e32[i];
        #pragma unroll
        for (int off = 16; off > 0; off >>= 1)
            nz |= __shfl_xor_sync(0xffffffffu, nz, off);
        if (lane == 0) sSc[wid] = nz;
        __syncthreads();
        if (tid == 0) {
            int r = 0;
            #pragma unroll
            for (int w = 0; w < 8; w++) r |= sSc[w];
            d_is64 = (r == 0) ? 1 : 0;
        }
        __syncthreads();
    }
    gemm_phase<0>(x, nullptr, nullptr, Wx, d_h1, N, sW);
    grid_barrier();                                            // B1

    const int is64 = d_is64;

    // ---- Phase B: degree histogram ----
    for (int e = gtid; e < E; e += nthr) {
        int d = load_idx(ei, E + e, is64);
        if ((unsigned)d < (unsigned)N) atomicAdd(&d_deg[d], 1);
    }
    grid_barrier();                                            // B2

    // ---- Phase C: per-tile local scan + dinv; LAST block does mid-scan ----
    const int ntiles = (N + 255) / 256;
    for (int tile = blockIdx.x; tile < ntiles; tile += NB) {
        int i = tile * 256 + tid;
        int v = (i < N) ? d_deg[i] : 0;
        if (i < N) d_dinv[i] = rsqrtf((float)v + 1.0f);
        int xv = v;
        #pragma unroll
        for (int off = 1; off < 32; off <<= 1) {
            int y = __shfl_up_sync(0xffffffffu, xv, off);
            if (lane >= off) xv += y;
        }
        if (lane == 31) sSc[wid] = xv;
        __syncthreads();
        if (wid == 0 && lane < 8) {
            int s2 = sSc[lane];
            #pragma unroll
            for (int off = 1; off < 8; off <<= 1) {
                int y = __shfl_up_sync(0xffu, s2, off);
                if (lane >= off) s2 += y;
            }
            sSc[lane] = s2;
        }
        __syncthreads();
        int incl = xv + ((wid > 0) ? sSc[wid - 1] : 0);
        if (i < N) {
            int excl = incl - v;
            d_rowptr[i] = excl;                    // tile-local
            d_cursor[i] = excl;
        }
        if (tid == 255) d_bsum[tile] = incl;
        __syncthreads();
    }
    // last-block ticket -> mid-scan of tile totals
    {
        __shared__ int amLast;
        __threadfence();
        __syncthreads();
        if (tid == 0) {
            unsigned t = atomicAdd(&d_p2done, 1u);
            amLast = (t == (unsigned)(NB - 1));
            if (amLast) d_p2done = 0;
        }
        __syncthreads();
        if (amLast) {
            __threadfence();                       // acquire bsum writes
            int v = (tid < ntiles) ? d_bsum[tid] : 0;
            int xv = v;
            #pragma unroll
            for (int off = 1; off < 32; off <<= 1) {
                int y = __shfl_up_sync(0xffffffffu, xv, off);
                if (lane >= off) xv += y;
            }
            if (lane == 31) sSc[wid] = xv;
            __syncthreads();
            if (wid == 0 && lane < 8) {
                int s2 = sSc[lane];
                #pragma unroll
                for (int off = 1; off < 8; off <<= 1) {
                    int y = __shfl_up_sync(0xffu, s2, off);
                    if (lane >= off) s2 += y;
                }
                sSc[lane] = s2;
            }
            __syncthreads();
            int incl = xv + ((wid > 0) ? sSc[wid - 1] : 0);
            if (tid < ntiles) d_boff[tid] = incl - v;
        }
    }
    grid_barrier();                                            // B3

    // ---- Phase D: CSR fill (global pos = local cursor + tile offset) ----
    for (int e = gtid; e < E; e += nthr) {
        int s = load_idx(ei, e, is64);
        int d = load_idx(ei, E + e, is64);
        if ((unsigned)s < (unsigned)N && (unsigned)d < (unsigned)N) {
            int p = atomicAdd(&d_cursor[d], 1) + d_boff[d >> 8];
            d_csr[p] = make_int2(s, __float_as_int(d_dinv[s] * d_dinv[d]));
        }
    }
    grid_barrier();                                            // B4

    // ---- Phases E..I: agg0, gemm1, agg1, gemm2, agg2 ----
    agg_phase<0>(d_h1, bx, nullptr, nullptr, d_xgcn, N, sCS);
    grid_barrier();                                            // B5

    gemm_phase<1>(d_xgcn, h_prev, nullptr, Wuh, d_h1, N, sW);
    grid_barrier();                                            // B6

    agg_phase<1>(d_h1, buh, nullptr, nullptr, d_g, N, sCS);
    grid_barrier();                                            // B7

    gemm_phase<2>(d_xgcn, h_prev, d_g, Wch, d_h1, N, sW);
    grid_barrier();                                            // B8

    agg_phase<2>(d_h1, bch, d_g, h_prev, out, N, sCS);
}

// ---------------- launch: ONE kernel ----------------
extern "C" void kernel_launch(void* const* d_in, const int* in_sizes, int n_in,
                              void* d_out, int out_size)
{
    const float* x      = (const float*)d_in[0];
    const void*  ei     = d_in[1];
    const float* h_prev = (const float*)d_in[2];
    const float* Wx     = (const float*)d_in[3];
    const float* bx     = (const float*)d_in[4];
    const float* Wuh    = (const float*)d_in[5];
    const float* buh    = (const float*)d_in[6];
    const float* Wch    = (const float*)d_in[7];
    const float* bch    = (const float*)d_in[8];
    float*       out    = (float*)d_out;

    int N = in_sizes[0] / C;
    int E = in_sizes[1] / 2;
    if (N > NMAX) N = NMAX;
    if (E > EMAX) E = EMAX;

    const int SMEM_BYTES = C * C * (int)sizeof(float) + 8 * 32 * (int)sizeof(int2);

    cudaFuncSetAttribute(mega_kernel,
                         cudaFuncAttributeMaxDynamicSharedMemorySize, SMEM_BYTES);

    int dev = 0;
    cudaGetDevice(&dev);
    int nsm = 148;
    cudaDeviceGetAttribute(&nsm, cudaDevAttrMultiProcessorCount, dev);
    int occ = 1;
    cudaOccupancyMaxActiveBlocksPerMultiprocessor(&occ, mega_kernel, 256, SMEM_BYTES);
    if (occ < 1) occ = 1;
    int grid = nsm * occ;   // guaranteed co-resident -> grid barrier is safe

    mega_kernel<<<grid, 256, SMEM_BYTES>>>(
        x, ei, h_prev, Wx, bx, Wuh, buh, Wch, bch, out, N, E);
}